// round 14
// baseline (speedup 1.0000x reference)
#include <cuda_runtime.h>
#include <cuda_fp16.h>
#include <mma.h>
#include <math.h>

using namespace nvcuda;

// Problem constants (fixed by the dataset)
#define E_NUM 32768
#define BATCH 128     // == H
#define DIM   1024    // IMG_DIM == TXT_DIM
#define KC    64      // GEMM k-chunk within a k-split
#define ASTR  72      // padded smem A row stride (halves)
#define BSTR  40      // padded smem B row stride (halves)
#define GEMM_SMEM (2 * 128 * ASTR * 2 + 2 * 64 * BSTR * 2)   // 47104 B

// ---- device scratch (allocation-free: __device__ globals) ----
__device__ __align__(16) float  g_imgT [DIM * BATCH];   // img^T  [i][b]
__device__ __align__(16) float  g_txtT [DIM * BATCH];   // text^T [t][b]
__device__ __align__(16) float  g_W1aT [BATCH * BATCH]; // W1[:, :128]^T [b][j]
__device__ __align__(16) float  g_W1bT [BATCH * BATCH]; // W1[:, 128:]^T [b][j]
__device__ __align__(16) __half g_UTh  [DIM * BATCH];   // (W1a@img + b1)^T fp16
__device__ __align__(16) __half g_VTh  [DIM * BATCH];   // (W1b@text)^T     fp16
__device__ __align__(16) __half g_img16[BATCH * DIM];   // img  [b][i] fp16
__device__ __align__(16) __half g_txt16[BATCH * DIM];   // text [b][t] fp16
__device__ __align__(16) __half g_P0   [DIM * DIM];     // P0[t][i] = a(i,t)
__device__ __align__(16) __half g_P1   [DIM * DIM];     // P1[i][t] = a(i,t)

// ---- prep: transposes + P zeroing + fp16 copies + d_out zeroing ----
__global__ void __launch_bounds__(512) k_prep(const float* __restrict__ img,
                                              const float* __restrict__ txt,
                                              const float* __restrict__ W1,
                                              float* __restrict__ out) {
    int id = blockIdx.x;
    int t  = threadIdx.x;

    if (id >= 304) {                       // zero d_out: 65536 float4
        float4* p = reinterpret_cast<float4*>(out) + (id - 304) * 2048;
        float4 z = make_float4(0.f, 0.f, 0.f, 0.f);
#pragma unroll
        for (int i = 0; i < 4; ++i)
            p[i * 512 + t] = z;
        return;
    }
    if (id >= 272) {                       // fp16 copies: 65536 float4 total
        int g0 = (id - 272) * 2048;
        const float4* fi = (const float4*)img;   // 32768 float4
        const float4* ft = (const float4*)txt;   // 32768 float4
#pragma unroll
        for (int i = 0; i < 4; ++i) {
            int g = g0 + i * 512 + t;
            bool isTxt = g >= 32768;
            int  li = isTxt ? g - 32768 : g;
            float4 v = isTxt ? ft[li] : fi[li];
            __half2 h01 = __floats2half2_rn(v.x, v.y);
            __half2 h23 = __floats2half2_rn(v.z, v.w);
            uint2 o = make_uint2(*reinterpret_cast<unsigned*>(&h01),
                                 *reinterpret_cast<unsigned*>(&h23));
            reinterpret_cast<uint2*>(isTxt ? g_txt16 : g_img16)[li] = o;
        }
        return;
    }
    if (id >= 144) {                       // zero P0/P1
        bool p1 = id >= 208;
        float4* p = reinterpret_cast<float4*>(p1 ? g_P1 : g_P0)
                  + ((id - (p1 ? 208 : 144)) * 2048);
        float4 z = make_float4(0.f, 0.f, 0.f, 0.f);
#pragma unroll
        for (int i = 0; i < 4; ++i)
            p[i * 512 + t] = z;
        return;
    }

    // transposes (128-row x 16-col strips, float4 in/out)
    __shared__ __align__(16) float sh[16 * 132];
    const float* in; float* o; int stride, c0;
    if (id < 64)        { in = img;        stride = DIM;       o = g_imgT; c0 = id * 16; }
    else if (id < 128)  { in = txt;        stride = DIM;       o = g_txtT; c0 = (id - 64) * 16; }
    else if (id < 136)  { in = W1;         stride = 2 * BATCH; o = g_W1aT; c0 = (id - 128) * 16; }
    else                { in = W1 + BATCH; stride = 2 * BATCH; o = g_W1bT; c0 = (id - 136) * 16; }
    {
        int r = t >> 2, x = t & 3;
        float4 v = *reinterpret_cast<const float4*>(in + (long)r * stride + c0 + 4 * x);
        sh[(4 * x + 0) * 132 + r] = v.x;
        sh[(4 * x + 1) * 132 + r] = v.y;
        sh[(4 * x + 2) * 132 + r] = v.z;
        sh[(4 * x + 3) * 132 + r] = v.w;
    }
    __syncthreads();
    {
        int c = t >> 5, k = t & 31;
        float4 v = reinterpret_cast<const float4*>(sh + c * 132)[k];
        reinterpret_cast<float4*>(o + (c0 + c) * BATCH)[k] = v;
    }
}

// ---- UT/VT (fp16 out) ----
__global__ void k_uv(const float* __restrict__ b1) {
    int  col = blockIdx.x & (DIM - 1);
    bool isV = blockIdx.x >= DIM;
    int  j   = threadIdx.x;

    float bias = isV ? 0.0f : b1[j];

    cudaGridDependencySynchronize();   // wait for k_prep

    const float* x  = (isV ? g_txtT : g_imgT) + col * BATCH;
    const float* Wt =  isV ? g_W1bT : g_W1aT;

    __shared__ float xs[BATCH];
    xs[j] = x[j];
    __syncthreads();

    float acc = bias;
#pragma unroll 16
    for (int b = 0; b < BATCH; ++b)
        acc = fmaf(Wt[b * BATCH + j], xs[b], acc);

    (isV ? g_VTh : g_UTh)[col * BATCH + j] = __float2half_rn(acc);
}

// ---- per-edge attention -> dense P matrices ----
__global__ void k_edge(const int* __restrict__ src, const int* __restrict__ tgt,
                       const float* __restrict__ w2, const float* __restrict__ b2) {
    int warp = threadIdx.x >> 5;
    int lane = threadIdx.x & 31;
    int e    = blockIdx.x * 8 + warp;

    int s = src[e];
    int t = tgt[e];
    float4 w = reinterpret_cast<const float4*>(w2)[lane];
    float bias2 = b2[0];

    cudaGridDependencySynchronize();   // wait for k_uv

    uint2 ur = reinterpret_cast<const uint2*>(g_UTh + s * BATCH)[lane];
    uint2 vr = reinterpret_cast<const uint2*>(g_VTh + t * BATCH)[lane];
    float2 u01 = __half22float2(*reinterpret_cast<__half2*>(&ur.x));
    float2 u23 = __half22float2(*reinterpret_cast<__half2*>(&ur.y));
    float2 v01 = __half22float2(*reinterpret_cast<__half2*>(&vr.x));
    float2 v23 = __half22float2(*reinterpret_cast<__half2*>(&vr.y));

    float h0 = fmaxf(u01.x + v01.x, 0.0f);
    float h1 = fmaxf(u01.y + v01.y, 0.0f);
    float h2 = fmaxf(u23.x + v23.x, 0.0f);
    float h3 = fmaxf(u23.y + v23.y, 0.0f);

    float p = fmaf(h0, w.x, fmaf(h1, w.y, fmaf(h2, w.z, h3 * w.w)));
#pragma unroll
    for (int off = 16; off; off >>= 1)
        p += __shfl_xor_sync(0xffffffffu, p, off);

    if (lane == 0) {
        float a = __fdividef(1.0f, 1.0f + __expf(-(p + bias2)));
        __half ah = __float2half_rn(a);
        g_P0[t * DIM + s] = ah;
        g_P1[s * DIM + t] = ah;
    }
}

// ---- split-K pipelined tensor-core GEMM, 2 blocks/SM ----
// grid (32 ntiles, 4 ksplits, 2 sides) = 256 blocks, 256 threads (8 warps).
// Block: rows 0..127, cols [32*nt,+32), K range [256*ks,+256) in 4 chunks of 64.
// Warp w: rows [16w,+16), 2 col-fragments. RED into d_out (zeroed by k_prep).
__global__ void __launch_bounds__(256) k_gemm(float* __restrict__ out) {
    extern __shared__ __align__(16) __half dyn[];
    __half* shA = dyn;                     // [2][128*ASTR]
    __half* shB = dyn + 2 * 128 * ASTR;    // [2][64*BSTR]

    int nt   = blockIdx.x;
    int ksp  = blockIdx.y;
    int side = blockIdx.z;
    int tid  = threadIdx.x;
    int w    = tid >> 5;
    int lane = tid & 31;

    cudaGridDependencySynchronize();   // wait for k_edge's P writes

    const __half* A = side ? g_img16 : g_txt16;  // [128][1024]
    const __half* B = side ? g_P1    : g_P0;     // [1024][1024]
    float* C = out + (size_t)side * BATCH * DIM;
    int col0 = nt * 32;
    int k0   = ksp * 256;

    auto stage = [&](int kc, int buf) {
        int kb = k0 + kc * KC;
        // A chunk: 128 x 64 halves = 1024 uint4, 4/thread
#pragma unroll
        for (int j = 0; j < 4; ++j) {
            int i  = tid + j * 256;
            int m  = i >> 3;
            int kk = (i & 7) * 8;
            unsigned sa = (unsigned)__cvta_generic_to_shared(
                &shA[buf * 128 * ASTR + m * ASTR + kk]);
            const __half* g = A + (long)m * DIM + kb + kk;
            asm volatile("cp.async.cg.shared.global [%0], [%1], 16;" :: "r"(sa), "l"(g));
        }
        // B chunk: 64 x 32 halves = 256 uint4, 1/thread
        {
            int r  = tid >> 2;
            int nn = (tid & 3) * 8;
            unsigned sb = (unsigned)__cvta_generic_to_shared(
                &shB[buf * 64 * BSTR + r * BSTR + nn]);
            const __half* g = B + (long)(kb + r) * DIM + col0 + nn;
            asm volatile("cp.async.cg.shared.global [%0], [%1], 16;" :: "r"(sb), "l"(g));
        }
        asm volatile("cp.async.commit_group;");
    };

    wmma::fragment<wmma::accumulator, 16, 16, 16, float> c[2];
    wmma::fill_fragment(c[0], 0.0f);
    wmma::fill_fragment(c[1], 0.0f);

    stage(0, 0);
    for (int kc = 0; kc < 4; ++kc) {
        int buf = kc & 1;
        if (kc < 3) {
            stage(kc + 1, buf ^ 1);
            asm volatile("cp.async.wait_group 1;" ::: "memory");
        } else {
            asm volatile("cp.async.wait_group 0;" ::: "memory");
        }
        __syncthreads();

#pragma unroll
        for (int ks = 0; ks < KC / 16; ++ks) {
            wmma::fragment<wmma::matrix_a, 16, 16, 16, __half, wmma::row_major> a;
            wmma::load_matrix_sync(a, &shA[buf * 128 * ASTR + (w * 16) * ASTR + ks * 16], ASTR);
#pragma unroll
            for (int cf = 0; cf < 2; ++cf) {
                wmma::fragment<wmma::matrix_b, 16, 16, 16, __half, wmma::row_major> b;
                wmma::load_matrix_sync(b, &shB[buf * 64 * BSTR + (ks * 16) * BSTR + cf * 16], BSTR);
                wmma::mma_sync(c[cf], a, b, c[cf]);
            }
        }
        __syncthreads();
    }

    // epilogue: fragments -> smem (warp-private) -> vectorized RED into d_out
    float* ep = reinterpret_cast<float*>(dyn) + w * (16 * 36);
    wmma::store_matrix_sync(ep,      c[0], 36, wmma::mem_row_major);
    wmma::store_matrix_sync(ep + 16, c[1], 36, wmma::mem_row_major);

    int m0 = w * 16;
#pragma unroll
    for (int it = 0; it < 4; ++it) {
        int idx = lane + it * 32;       // 128 float4 per warp
        int r  = idx >> 3;              // 0..15
        int c4 = idx & 7;               // 0..7 (16B groups)
        float4 v = *reinterpret_cast<const float4*>(ep + r * 36 + c4 * 4);
        float* gp = C + (long)(m0 + r) * DIM + col0 + c4 * 4;
        asm volatile("red.global.v4.f32.add [%0], {%1, %2, %3, %4};"
                     :: "l"(gp), "f"(v.x), "f"(v.y), "f"(v.z), "f"(v.w)
                     : "memory");
    }
}

extern "C" void kernel_launch(void* const* d_in, const int* in_sizes, int n_in,
                              void* d_out, int out_size) {
    const float* img = (const float*)d_in[0];   // [128, 1024]
    const float* txt = (const float*)d_in[1];   // [128, 1024]
    const int*   src = (const int*)  d_in[2];   // [32768]
    const int*   tgt = (const int*)  d_in[3];   // [32768]
    const float* W1  = (const float*)d_in[4];   // [128, 256]
    const float* b1  = (const float*)d_in[5];   // [128]
    const float* w2  = (const float*)d_in[6];   // [128]
    const float* b2  = (const float*)d_in[7];   // [1]
    float* out = (float*)d_out;                 // [2 * 128 * 1024]

    cudaFuncSetAttribute(k_gemm, cudaFuncAttributeMaxDynamicSharedMemorySize, GEMM_SMEM);

    cudaLaunchAttribute attr;
    attr.id = cudaLaunchAttributeProgrammaticStreamSerialization;
    attr.val.programmaticStreamSerializationAllowed = 1;

    // 1) transposes + P zeroing + fp16 copies + d_out zeroing
    {
        cudaLaunchConfig_t cfg = {};
        cfg.gridDim  = dim3(336);
        cfg.blockDim = dim3(512);
        cfg.attrs = &attr;
        cfg.numAttrs = 1;
        cudaLaunchKernelEx(&cfg, k_prep, img, txt, W1, out);
    }

    // 2) U/V GEMMs (fp16 out)
    {
        cudaLaunchConfig_t cfg = {};
        cfg.gridDim  = dim3(2 * DIM);
        cfg.blockDim = dim3(BATCH);
        cfg.attrs = &attr;
        cfg.numAttrs = 1;
        cudaLaunchKernelEx(&cfg, k_uv, b1);
    }

    // 3) per-edge MLP -> dense P matrices
    {
        cudaLaunchConfig_t cfg = {};
        cfg.gridDim  = dim3(E_NUM / 8);
        cfg.blockDim = dim3(256);
        cfg.attrs = &attr;
        cfg.numAttrs = 1;
        cudaLaunchKernelEx(&cfg, k_edge, src, tgt, w2, b2);
    }

    // 4) split-K tensor-core GEMMs (256 blocks) -> RED into d_out
    {
        cudaLaunchConfig_t cfg = {};
        cfg.gridDim  = dim3(32, 4, 2);
        cfg.blockDim = dim3(256);
        cfg.dynamicSmemBytes = GEMM_SMEM;
        cfg.attrs = &attr;
        cfg.numAttrs = 1;
        cudaLaunchKernelEx(&cfg, k_gemm, out);
    }
}

// round 15
// speedup vs baseline: 1.0949x; 1.0949x over previous
#include <cuda_runtime.h>
#include <cuda_fp16.h>
#include <mma.h>
#include <math.h>

using namespace nvcuda;

// Problem constants (fixed by the dataset)
#define E_NUM 32768
#define BATCH 128     // == H
#define DIM   1024    // IMG_DIM == TXT_DIM
#define KC    64      // GEMM k-chunk within a k-split
#define ASTR  72      // padded smem row stride (halves)
#define GEMM_SMEM (2 * 128 * ASTR * 2 + 2 * 64 * ASTR * 2)   // 55296 B

// ---- device scratch (allocation-free: __device__ globals) ----
__device__ __align__(16) __half g_W116 [BATCH * 2 * BATCH]; // W1 fp16 [128][256]
__device__ __align__(16) __half g_UTh  [DIM * BATCH];   // U^T [s][j] fp16
__device__ __align__(16) __half g_VTh  [DIM * BATCH];   // V^T [t][j] fp16
__device__ __align__(16) __half g_img16[BATCH * DIM];   // img  [b][i] fp16
__device__ __align__(16) __half g_txt16[BATCH * DIM];   // text [b][t] fp16
__device__ __align__(16) __half g_P0   [DIM * DIM];     // P0[t][i] = a(i,t)
__device__ __align__(16) __half g_P1   [DIM * DIM];     // P1[i][t] = a(i,t)

// ---- prep: pure copies + zeroing (no transposes, no smem) ----
// [0,128): zero P0/P1   [128,160): zero d_out
// [160,192): fp16 copies img/txt   [192,194): fp16 copy W1
__global__ void __launch_bounds__(512) k_prep(const float* __restrict__ img,
                                              const float* __restrict__ txt,
                                              const float* __restrict__ W1,
                                              float* __restrict__ out) {
    int id = blockIdx.x;
    int t  = threadIdx.x;

    if (id < 128) {                        // zero P0/P1: 4MB total
        bool p1 = id >= 64;
        float4* p = reinterpret_cast<float4*>(p1 ? g_P1 : g_P0)
                  + ((id & 63) * 2048);
        float4 z = make_float4(0.f, 0.f, 0.f, 0.f);
#pragma unroll
        for (int i = 0; i < 4; ++i)
            p[i * 512 + t] = z;
        return;
    }
    if (id < 160) {                        // zero d_out: 65536 float4
        float4* p = reinterpret_cast<float4*>(out) + (id - 128) * 2048;
        float4 z = make_float4(0.f, 0.f, 0.f, 0.f);
#pragma unroll
        for (int i = 0; i < 4; ++i)
            p[i * 512 + t] = z;
        return;
    }
    if (id < 192) {                        // fp16 copies: 65536 float4 total
        int g0 = (id - 160) * 2048;
        const float4* fi = (const float4*)img;   // 32768 float4
        const float4* ft = (const float4*)txt;   // 32768 float4
#pragma unroll
        for (int i = 0; i < 4; ++i) {
            int g = g0 + i * 512 + t;
            bool isTxt = g >= 32768;
            int  li = isTxt ? g - 32768 : g;
            float4 v = isTxt ? ft[li] : fi[li];
            __half2 h01 = __floats2half2_rn(v.x, v.y);
            __half2 h23 = __floats2half2_rn(v.z, v.w);
            uint2 o = make_uint2(*reinterpret_cast<unsigned*>(&h01),
                                 *reinterpret_cast<unsigned*>(&h23));
            reinterpret_cast<uint2*>(isTxt ? g_txt16 : g_img16)[li] = o;
        }
        return;
    }
    {                                      // fp16 copy of W1: 8192 float4
        int g0 = (id - 192) * 4096;
        const float4* fw = (const float4*)W1;
#pragma unroll
        for (int i = 0; i < 8; ++i) {
            int g = g0 + i * 512 + t;
            float4 v = fw[g];
            __half2 h01 = __floats2half2_rn(v.x, v.y);
            __half2 h23 = __floats2half2_rn(v.z, v.w);
            uint2 o = make_uint2(*reinterpret_cast<unsigned*>(&h01),
                                 *reinterpret_cast<unsigned*>(&h23));
            reinterpret_cast<uint2*>(g_W116)[g] = o;
        }
    }
}

// ---- UV via tensor cores: U[j][s] = sum_b W1a[j][b]*img16[b][s] (no bias —
// b1 is added in k_edge). Stored TRANSPOSED (col-major) into UTh[s][j] fp16.
// grid (64 s-tiles, 2 sides), block 256 (8 warps); warp w: j rows [16w,+16).
__global__ void __launch_bounds__(256) k_uvw() {
    __shared__ __align__(16) float eps[8][16 * 16];
    int s0   = blockIdx.x * 16;
    int side = blockIdx.y;             // 0: U from img/W1a; 1: V from txt/W1b
    int w    = threadIdx.x >> 5;
    int lane = threadIdx.x & 31;

    cudaGridDependencySynchronize();   // wait for k_prep's fp16 copies

    const __half* A = g_W116 + (side ? BATCH : 0);      // [128][256] row-major
    const __half* B = side ? g_txt16 : g_img16;         // [128][1024] row-major
    __half* O = side ? g_VTh : g_UTh;                   // [1024][128]

    wmma::fragment<wmma::accumulator, 16, 16, 16, float> acc;
    wmma::fill_fragment(acc, 0.0f);
#pragma unroll
    for (int k = 0; k < 8; ++k) {
        wmma::fragment<wmma::matrix_a, 16, 16, 16, __half, wmma::row_major> a;
        wmma::fragment<wmma::matrix_b, 16, 16, 16, __half, wmma::row_major> b;
        wmma::load_matrix_sync(a, A + (w * 16) * (2 * BATCH) + k * 16, 2 * BATCH);
        wmma::load_matrix_sync(b, B + (long)(k * 16) * DIM + s0, DIM);
        wmma::mma_sync(acc, a, b, acc);
    }

    // fragment -> smem (col-major: (j,s) at [j + s*16]) -> fp16 global
    wmma::store_matrix_sync(eps[w], acc, 16, wmma::mem_col_major);
    __syncwarp();
    int s  = lane >> 1;                // 0..15
    int j0 = (lane & 1) * 8;           // 0 or 8
    const float* src = eps[w] + s * 16 + j0;
    __half2 h0 = __floats2half2_rn(src[0], src[1]);
    __half2 h1 = __floats2half2_rn(src[2], src[3]);
    __half2 h2 = __floats2half2_rn(src[4], src[5]);
    __half2 h3 = __floats2half2_rn(src[6], src[7]);
    uint4 o = make_uint4(*reinterpret_cast<unsigned*>(&h0),
                         *reinterpret_cast<unsigned*>(&h1),
                         *reinterpret_cast<unsigned*>(&h2),
                         *reinterpret_cast<unsigned*>(&h3));
    *reinterpret_cast<uint4*>(O + (long)(s0 + s) * BATCH + w * 16 + j0) = o;
}

// ---- per-edge attention -> dense P matrices (b1 added here, in fp32) ----
__global__ void k_edge(const int* __restrict__ src, const int* __restrict__ tgt,
                       const float* __restrict__ w2, const float* __restrict__ b1,
                       const float* __restrict__ b2) {
    int warp = threadIdx.x >> 5;
    int lane = threadIdx.x & 31;
    int e    = blockIdx.x * 8 + warp;

    int s = src[e];
    int t = tgt[e];
    float4 w  = reinterpret_cast<const float4*>(w2)[lane];
    float4 bb = reinterpret_cast<const float4*>(b1)[lane];
    float bias2 = b2[0];

    cudaGridDependencySynchronize();   // wait for k_uvw

    uint2 ur = reinterpret_cast<const uint2*>(g_UTh + s * BATCH)[lane];
    uint2 vr = reinterpret_cast<const uint2*>(g_VTh + t * BATCH)[lane];
    float2 u01 = __half22float2(*reinterpret_cast<__half2*>(&ur.x));
    float2 u23 = __half22float2(*reinterpret_cast<__half2*>(&ur.y));
    float2 v01 = __half22float2(*reinterpret_cast<__half2*>(&vr.x));
    float2 v23 = __half22float2(*reinterpret_cast<__half2*>(&vr.y));

    float h0 = fmaxf(u01.x + v01.x + bb.x, 0.0f);
    float h1 = fmaxf(u01.y + v01.y + bb.y, 0.0f);
    float h2 = fmaxf(u23.x + v23.x + bb.z, 0.0f);
    float h3 = fmaxf(u23.y + v23.y + bb.w, 0.0f);

    float p = fmaf(h0, w.x, fmaf(h1, w.y, fmaf(h2, w.z, h3 * w.w)));
#pragma unroll
    for (int off = 16; off; off >>= 1)
        p += __shfl_xor_sync(0xffffffffu, p, off);

    if (lane == 0) {
        float a = __fdividef(1.0f, 1.0f + __expf(-(p + bias2)));
        __half ah = __float2half_rn(a);
        g_P0[t * DIM + s] = ah;
        g_P1[s * DIM + t] = ah;
    }
}

// ---- split-K pipelined tensor-core GEMM (R13 config: best measured) ----
// grid (16 ntiles, 4 ksplits, 2 sides) = 128 blocks, 256 threads (8 warps).
__global__ void __launch_bounds__(256) k_gemm(float* __restrict__ out) {
    extern __shared__ __align__(16) __half dyn[];
    __half* shA = dyn;                     // [2][128*ASTR]
    __half* shB = dyn + 2 * 128 * ASTR;    // [2][64*ASTR]

    int nt   = blockIdx.x;
    int ksp  = blockIdx.y;
    int side = blockIdx.z;
    int tid  = threadIdx.x;
    int w    = tid >> 5;
    int lane = tid & 31;

    cudaGridDependencySynchronize();   // wait for k_edge's P writes

    const __half* A = side ? g_img16 : g_txt16;  // [128][1024]
    const __half* B = side ? g_P1    : g_P0;     // [1024][1024]
    float* C = out + (size_t)side * BATCH * DIM;
    int col0 = nt * 64;
    int k0   = ksp * 256;

    auto stage = [&](int kc, int buf) {
        int kb = k0 + kc * KC;
#pragma unroll
        for (int j = 0; j < 4; ++j) {
            int i  = tid + j * 256;
            int m  = i >> 3;
            int kk = (i & 7) * 8;
            unsigned sa = (unsigned)__cvta_generic_to_shared(
                &shA[buf * 128 * ASTR + m * ASTR + kk]);
            const __half* g = A + (long)m * DIM + kb + kk;
            asm volatile("cp.async.cg.shared.global [%0], [%1], 16;" :: "r"(sa), "l"(g));
        }
#pragma unroll
        for (int j = 0; j < 2; ++j) {
            int i  = tid + j * 256;
            int r  = i >> 3;
            int nn = (i & 7) * 8;
            unsigned sb = (unsigned)__cvta_generic_to_shared(
                &shB[buf * 64 * ASTR + r * ASTR + nn]);
            const __half* g = B + (long)(kb + r) * DIM + col0 + nn;
            asm volatile("cp.async.cg.shared.global [%0], [%1], 16;" :: "r"(sb), "l"(g));
        }
        asm volatile("cp.async.commit_group;");
    };

    wmma::fragment<wmma::accumulator, 16, 16, 16, float> c[4];
#pragma unroll
    for (int i = 0; i < 4; ++i) wmma::fill_fragment(c[i], 0.0f);

    stage(0, 0);
    for (int kc = 0; kc < 4; ++kc) {
        int buf = kc & 1;
        if (kc < 3) {
            stage(kc + 1, buf ^ 1);
            asm volatile("cp.async.wait_group 1;" ::: "memory");
        } else {
            asm volatile("cp.async.wait_group 0;" ::: "memory");
        }
        __syncthreads();

#pragma unroll
        for (int ks = 0; ks < KC / 16; ++ks) {
            wmma::fragment<wmma::matrix_a, 16, 16, 16, __half, wmma::row_major> a;
            wmma::load_matrix_sync(a, &shA[buf * 128 * ASTR + (w * 16) * ASTR + ks * 16], ASTR);
#pragma unroll
            for (int cf = 0; cf < 4; ++cf) {
                wmma::fragment<wmma::matrix_b, 16, 16, 16, __half, wmma::row_major> b;
                wmma::load_matrix_sync(b, &shB[buf * 64 * ASTR + (ks * 16) * ASTR + cf * 16], ASTR);
                wmma::mma_sync(c[cf], a, b, c[cf]);
            }
        }
        __syncthreads();
    }

    // epilogue: fragments -> smem (warp-private) -> vectorized RED into d_out
    float* ep = reinterpret_cast<float*>(dyn) + w * (16 * 68);
#pragma unroll
    for (int cf = 0; cf < 4; ++cf)
        wmma::store_matrix_sync(ep + cf * 16, c[cf], 68, wmma::mem_row_major);

    int m0 = w * 16;
#pragma unroll
    for (int it = 0; it < 8; ++it) {
        int idx = lane + it * 32;
        int r  = idx >> 4;
        int c4 = idx & 15;
        float4 v = *reinterpret_cast<const float4*>(ep + r * 68 + c4 * 4);
        float* gp = C + (long)(m0 + r) * DIM + col0 + c4 * 4;
        asm volatile("red.global.v4.f32.add [%0], {%1, %2, %3, %4};"
                     :: "l"(gp), "f"(v.x), "f"(v.y), "f"(v.z), "f"(v.w)
                     : "memory");
    }
}

extern "C" void kernel_launch(void* const* d_in, const int* in_sizes, int n_in,
                              void* d_out, int out_size) {
    const float* img = (const float*)d_in[0];   // [128, 1024]
    const float* txt = (const float*)d_in[1];   // [128, 1024]
    const int*   src = (const int*)  d_in[2];   // [32768]
    const int*   tgt = (const int*)  d_in[3];   // [32768]
    const float* W1  = (const float*)d_in[4];   // [128, 256]
    const float* b1  = (const float*)d_in[5];   // [128]
    const float* w2  = (const float*)d_in[6];   // [128]
    const float* b2  = (const float*)d_in[7];   // [1]
    float* out = (float*)d_out;                 // [2 * 128 * 1024]

    cudaFuncSetAttribute(k_gemm, cudaFuncAttributeMaxDynamicSharedMemorySize, GEMM_SMEM);

    cudaLaunchAttribute attr;
    attr.id = cudaLaunchAttributeProgrammaticStreamSerialization;
    attr.val.programmaticStreamSerializationAllowed = 1;

    // 1) copies + zeroing (no transposes)
    {
        cudaLaunchConfig_t cfg = {};
        cfg.gridDim  = dim3(194);
        cfg.blockDim = dim3(512);
        cfg.attrs = &attr;
        cfg.numAttrs = 1;
        cudaLaunchKernelEx(&cfg, k_prep, img, txt, W1, out);
    }

    // 2) U/V via tensor cores (col-major store -> transposed fp16)
    {
        cudaLaunchConfig_t cfg = {};
        cfg.gridDim  = dim3(64, 2);
        cfg.blockDim = dim3(256);
        cfg.attrs = &attr;
        cfg.numAttrs = 1;
        cudaLaunchKernelEx(&cfg, k_uvw);
    }

    // 3) per-edge MLP (b1 added here) -> dense P matrices
    {
        cudaLaunchConfig_t cfg = {};
        cfg.gridDim  = dim3(E_NUM / 8);
        cfg.blockDim = dim3(256);
        cfg.attrs = &attr;
        cfg.numAttrs = 1;
        cudaLaunchKernelEx(&cfg, k_edge, src, tgt, w2, b1, b2);
    }

    // 4) split-K tensor-core GEMMs -> RED into d_out
    {
        cudaLaunchConfig_t cfg = {};
        cfg.gridDim  = dim3(16, 4, 2);
        cfg.blockDim = dim3(256);
        cfg.dynamicSmemBytes = GEMM_SMEM;
        cfg.attrs = &attr;
        cfg.numAttrs = 1;
        cudaLaunchKernelEx(&cfg, k_gemm, out);
    }
}

// round 16
// speedup vs baseline: 1.3795x; 1.2600x over previous
#include <cuda_runtime.h>
#include <cuda_fp16.h>
#include <mma.h>
#include <math.h>

using namespace nvcuda;

// Problem constants (fixed by the dataset)
#define E_NUM 32768
#define BATCH 128     // == H
#define DIM   1024    // IMG_DIM == TXT_DIM
#define KC    64      // GEMM k-chunk within a k-split
#define ASTR  72      // padded smem row stride (halves)
#define WSTR  136     // padded W1 smem stride (halves)
#define GEMM_SMEM (2 * 128 * ASTR * 2 + 2 * 64 * ASTR * 2)   // 55296 B

// ---- device scratch (allocation-free: __device__ globals) ----
__device__ __align__(16) __half g_UTh  [DIM * BATCH];   // U^T [s][j] fp16
__device__ __align__(16) __half g_VTh  [DIM * BATCH];   // V^T [t][j] fp16
__device__ __align__(16) __half g_img16[BATCH * DIM];   // img  [b][i] fp16
__device__ __align__(16) __half g_txt16[BATCH * DIM];   // text [b][t] fp16
__device__ __align__(16) __half g_P0   [DIM * DIM];     // P0[t][i] = a(i,t)
__device__ __align__(16) __half g_P1   [DIM * DIM];     // P1[i][t] = a(i,t)

// ---- UV via tensor cores, fully self-sufficient (FIRST kernel, no sync) ----
// U[j][s] = sum_b W1a[j][b]*img[b][s]  (V analogous from W1b/txt; b1 added in
// k_edge). Converts its own W1 half + feature tile fp32->fp16 in smem and
// zeroes its slice of P0/P1.
// grid (64 s-tiles, 2 sides) = 128 blocks, 256 thr (8 warps).
__global__ void __launch_bounds__(256) k_uvw(const float* __restrict__ img,
                                             const float* __restrict__ txt,
                                             const float* __restrict__ W1) {
    __shared__ __align__(16) __half sW[128 * WSTR];   // W1 side [j][b]
    __shared__ __align__(16) __half sF[128 * 16];     // feature tile [b][sc]
    __shared__ __align__(16) float  eps[8][16 * 16];

    int s0   = blockIdx.x * 16;
    int side = blockIdx.y;             // 0: U from img/W1a; 1: V from txt/W1b
    int tid  = threadIdx.x;
    int w    = tid >> 5;
    int lane = tid & 31;

    // zero P slice: 4MB total / 128 blocks = 1024 float4 of each P per block
    {
        int bid = side * 64 + blockIdx.x;
        float4 z = make_float4(0.f, 0.f, 0.f, 0.f);
        float4* p0 = reinterpret_cast<float4*>(g_P0) + bid * 1024;
        float4* p1 = reinterpret_cast<float4*>(g_P1) + bid * 1024;
#pragma unroll
        for (int i = 0; i < 4; ++i) {
            p0[i * 256 + tid] = z;
            p1[i * 256 + tid] = z;
        }
    }

    // convert W1 half: [128][128] fp32 -> sW fp16 (4096 float4, 16/thread)
    const float* Wsrc = W1 + side * BATCH;
#pragma unroll
    for (int i = 0; i < 16; ++i) {
        int g  = tid + i * 256;        // 0..4095
        int r  = g >> 5;               // 32 float4 per row
        int c4 = g & 31;
        float4 v = *reinterpret_cast<const float4*>(Wsrc + r * 2 * BATCH + c4 * 4);
        __half2 h01 = __floats2half2_rn(v.x, v.y);
        __half2 h23 = __floats2half2_rn(v.z, v.w);
        uint2 o = make_uint2(*reinterpret_cast<unsigned*>(&h01),
                             *reinterpret_cast<unsigned*>(&h23));
        *reinterpret_cast<uint2*>(&sW[r * WSTR + c4 * 4]) = o;
    }

    // convert feature tile: rows 0..127, cols [s0,s0+16) (512 float4, 2/thread)
    const float* feat = side ? txt : img;
#pragma unroll
    for (int i = 0; i < 2; ++i) {
        int g  = tid + i * 256;        // 0..511
        int r  = g >> 2;               // 4 float4 per row
        int c4 = g & 3;
        float4 v = *reinterpret_cast<const float4*>(feat + (long)r * DIM + s0 + c4 * 4);
        __half2 h01 = __floats2half2_rn(v.x, v.y);
        __half2 h23 = __floats2half2_rn(v.z, v.w);
        uint2 o = make_uint2(*reinterpret_cast<unsigned*>(&h01),
                             *reinterpret_cast<unsigned*>(&h23));
        *reinterpret_cast<uint2*>(&sF[r * 16 + c4 * 4]) = o;
    }
    __syncthreads();

    wmma::fragment<wmma::accumulator, 16, 16, 16, float> acc;
    wmma::fill_fragment(acc, 0.0f);
#pragma unroll
    for (int k = 0; k < 8; ++k) {
        wmma::fragment<wmma::matrix_a, 16, 16, 16, __half, wmma::row_major> a;
        wmma::fragment<wmma::matrix_b, 16, 16, 16, __half, wmma::row_major> b;
        wmma::load_matrix_sync(a, &sW[(w * 16) * WSTR + k * 16], WSTR);
        wmma::load_matrix_sync(b, &sF[(k * 16) * 16], 16);
        wmma::mma_sync(acc, a, b, acc);
    }

    // fragment -> smem (col-major: (j,s) at [s*16 + j]) -> fp16 global
    wmma::store_matrix_sync(eps[w], acc, 16, wmma::mem_col_major);
    __syncwarp();
    int s  = lane >> 1;                // 0..15
    int j0 = (lane & 1) * 8;           // 0 or 8
    __half* O = side ? g_VTh : g_UTh;
    const float* sp = eps[w] + s * 16 + j0;
    __half2 h0 = __floats2half2_rn(sp[0], sp[1]);
    __half2 h1 = __floats2half2_rn(sp[2], sp[3]);
    __half2 h2 = __floats2half2_rn(sp[4], sp[5]);
    __half2 h3 = __floats2half2_rn(sp[6], sp[7]);
    uint4 o = make_uint4(*reinterpret_cast<unsigned*>(&h0),
                         *reinterpret_cast<unsigned*>(&h1),
                         *reinterpret_cast<unsigned*>(&h2),
                         *reinterpret_cast<unsigned*>(&h3));
    *reinterpret_cast<uint4*>(O + (long)(s0 + s) * BATCH + w * 16 + j0) = o;
}

// ---- per-edge attention -> dense P matrices ----
// Pre-sync side-work: fp16 copies of img/txt (for gemm) + d_out zeroing.
__global__ void k_edge(const int* __restrict__ src, const int* __restrict__ tgt,
                       const float* __restrict__ w2, const float* __restrict__ b1,
                       const float* __restrict__ b2,
                       const float* __restrict__ img, const float* __restrict__ txt,
                       float* __restrict__ out) {
    int tid  = threadIdx.x;
    int warp = tid >> 5;
    int lane = tid & 31;
    int e    = blockIdx.x * 8 + warp;

    // ---- pre-sync: independent of k_uvw ----
    // fp16 copies: 65536 float4 / 4096 blocks = 16/block (threads 0..15)
    if (tid < 16) {
        int g = blockIdx.x * 16 + tid;
        bool isTxt = g >= 32768;
        int  li = isTxt ? g - 32768 : g;
        float4 v = isTxt ? reinterpret_cast<const float4*>(txt)[li]
                         : reinterpret_cast<const float4*>(img)[li];
        __half2 h01 = __floats2half2_rn(v.x, v.y);
        __half2 h23 = __floats2half2_rn(v.z, v.w);
        uint2 o = make_uint2(*reinterpret_cast<unsigned*>(&h01),
                             *reinterpret_cast<unsigned*>(&h23));
        reinterpret_cast<uint2*>(isTxt ? g_txt16 : g_img16)[li] = o;
    } else if (tid < 32) {
        // zero d_out: 65536 float4 / 4096 blocks = 16/block (threads 16..31)
        int g = blockIdx.x * 16 + (tid - 16);
        reinterpret_cast<float4*>(out)[g] = make_float4(0.f, 0.f, 0.f, 0.f);
    }

    int s = src[e];
    int t = tgt[e];
    float4 w  = reinterpret_cast<const float4*>(w2)[lane];
    float4 bb = reinterpret_cast<const float4*>(b1)[lane];
    float bias2 = b2[0];

    cudaGridDependencySynchronize();   // wait for k_uvw (UTh/VTh + P zeroing)

    uint2 ur = reinterpret_cast<const uint2*>(g_UTh + s * BATCH)[lane];
    uint2 vr = reinterpret_cast<const uint2*>(g_VTh + t * BATCH)[lane];
    float2 u01 = __half22float2(*reinterpret_cast<__half2*>(&ur.x));
    float2 u23 = __half22float2(*reinterpret_cast<__half2*>(&ur.y));
    float2 v01 = __half22float2(*reinterpret_cast<__half2*>(&vr.x));
    float2 v23 = __half22float2(*reinterpret_cast<__half2*>(&vr.y));

    float h0 = fmaxf(u01.x + v01.x + bb.x, 0.0f);
    float h1 = fmaxf(u01.y + v01.y + bb.y, 0.0f);
    float h2 = fmaxf(u23.x + v23.x + bb.z, 0.0f);
    float h3 = fmaxf(u23.y + v23.y + bb.w, 0.0f);

    float p = fmaf(h0, w.x, fmaf(h1, w.y, fmaf(h2, w.z, h3 * w.w)));
#pragma unroll
    for (int off = 16; off; off >>= 1)
        p += __shfl_xor_sync(0xffffffffu, p, off);

    if (lane == 0) {
        float a = __fdividef(1.0f, 1.0f + __expf(-(p + bias2)));
        __half ah = __float2half_rn(a);
        g_P0[t * DIM + s] = ah;
        g_P1[s * DIM + t] = ah;
    }
}

// ---- split-K pipelined tensor-core GEMM (best-measured config) ----
// grid (16 ntiles, 4 ksplits, 2 sides) = 128 blocks, 256 threads (8 warps).
__global__ void __launch_bounds__(256) k_gemm(float* __restrict__ out) {
    extern __shared__ __align__(16) __half dyn[];
    __half* shA = dyn;                     // [2][128*ASTR]
    __half* shB = dyn + 2 * 128 * ASTR;    // [2][64*ASTR]

    int nt   = blockIdx.x;
    int ksp  = blockIdx.y;
    int side = blockIdx.z;
    int tid  = threadIdx.x;
    int w    = tid >> 5;
    int lane = tid & 31;

    cudaGridDependencySynchronize();   // wait for k_edge (P writes, img16, d_out=0)

    const __half* A = side ? g_img16 : g_txt16;  // [128][1024]
    const __half* B = side ? g_P1    : g_P0;     // [1024][1024]
    float* C = out + (size_t)side * BATCH * DIM;
    int col0 = nt * 64;
    int k0   = ksp * 256;

    auto stage = [&](int kc, int buf) {
        int kb = k0 + kc * KC;
#pragma unroll
        for (int j = 0; j < 4; ++j) {
            int i  = tid + j * 256;
            int m  = i >> 3;
            int kk = (i & 7) * 8;
            unsigned sa = (unsigned)__cvta_generic_to_shared(
                &shA[buf * 128 * ASTR + m * ASTR + kk]);
            const __half* g = A + (long)m * DIM + kb + kk;
            asm volatile("cp.async.cg.shared.global [%0], [%1], 16;" :: "r"(sa), "l"(g));
        }
#pragma unroll
        for (int j = 0; j < 2; ++j) {
            int i  = tid + j * 256;
            int r  = i >> 3;
            int nn = (i & 7) * 8;
            unsigned sb = (unsigned)__cvta_generic_to_shared(
                &shB[buf * 64 * ASTR + r * ASTR + nn]);
            const __half* g = B + (long)(kb + r) * DIM + col0 + nn;
            asm volatile("cp.async.cg.shared.global [%0], [%1], 16;" :: "r"(sb), "l"(g));
        }
        asm volatile("cp.async.commit_group;");
    };

    wmma::fragment<wmma::accumulator, 16, 16, 16, float> c[4];
#pragma unroll
    for (int i = 0; i < 4; ++i) wmma::fill_fragment(c[i], 0.0f);

    stage(0, 0);
    for (int kc = 0; kc < 4; ++kc) {
        int buf = kc & 1;
        if (kc < 3) {
            stage(kc + 1, buf ^ 1);
            asm volatile("cp.async.wait_group 1;" ::: "memory");
        } else {
            asm volatile("cp.async.wait_group 0;" ::: "memory");
        }
        __syncthreads();

#pragma unroll
        for (int ks = 0; ks < KC / 16; ++ks) {
            wmma::fragment<wmma::matrix_a, 16, 16, 16, __half, wmma::row_major> a;
            wmma::load_matrix_sync(a, &shA[buf * 128 * ASTR + (w * 16) * ASTR + ks * 16], ASTR);
#pragma unroll
            for (int cf = 0; cf < 4; ++cf) {
                wmma::fragment<wmma::matrix_b, 16, 16, 16, __half, wmma::row_major> b;
                wmma::load_matrix_sync(b, &shB[buf * 64 * ASTR + (ks * 16) * ASTR + cf * 16], ASTR);
                wmma::mma_sync(c[cf], a, b, c[cf]);
            }
        }
        __syncthreads();
    }

    // epilogue: fragments -> smem (warp-private) -> vectorized RED into d_out
    float* ep = reinterpret_cast<float*>(dyn) + w * (16 * 68);
#pragma unroll
    for (int cf = 0; cf < 4; ++cf)
        wmma::store_matrix_sync(ep + cf * 16, c[cf], 68, wmma::mem_row_major);

    int m0 = w * 16;
#pragma unroll
    for (int it = 0; it < 8; ++it) {
        int idx = lane + it * 32;
        int r  = idx >> 4;
        int c4 = idx & 15;
        float4 v = *reinterpret_cast<const float4*>(ep + r * 68 + c4 * 4);
        float* gp = C + (long)(m0 + r) * DIM + col0 + c4 * 4;
        asm volatile("red.global.v4.f32.add [%0], {%1, %2, %3, %4};"
                     :: "l"(gp), "f"(v.x), "f"(v.y), "f"(v.z), "f"(v.w)
                     : "memory");
    }
}

extern "C" void kernel_launch(void* const* d_in, const int* in_sizes, int n_in,
                              void* d_out, int out_size) {
    const float* img = (const float*)d_in[0];   // [128, 1024]
    const float* txt = (const float*)d_in[1];   // [128, 1024]
    const int*   src = (const int*)  d_in[2];   // [32768]
    const int*   tgt = (const int*)  d_in[3];   // [32768]
    const float* W1  = (const float*)d_in[4];   // [128, 256]
    const float* b1  = (const float*)d_in[5];   // [128]
    const float* w2  = (const float*)d_in[6];   // [128]
    const float* b2  = (const float*)d_in[7];   // [1]
    float* out = (float*)d_out;                 // [2 * 128 * 1024]

    cudaFuncSetAttribute(k_gemm, cudaFuncAttributeMaxDynamicSharedMemorySize, GEMM_SMEM);

    cudaLaunchAttribute attr;
    attr.id = cudaLaunchAttributeProgrammaticStreamSerialization;
    attr.val.programmaticStreamSerializationAllowed = 1;

    // 1) U/V via tensor cores (self-sufficient; also zeroes P0/P1)
    {
        cudaLaunchConfig_t cfg = {};
        cfg.gridDim  = dim3(64, 2);
        cfg.blockDim = dim3(256);
        cfg.attrs = &attr;
        cfg.numAttrs = 1;
        cudaLaunchKernelEx(&cfg, k_uvw, img, txt, W1);
    }

    // 2) per-edge MLP -> dense P; pre-sync: fp16 copies + d_out zeroing
    {
        cudaLaunchConfig_t cfg = {};
        cfg.gridDim  = dim3(E_NUM / 8);
        cfg.blockDim = dim3(256);
        cfg.attrs = &attr;
        cfg.numAttrs = 1;
        cudaLaunchKernelEx(&cfg, k_edge, src, tgt, w2, b1, b2, img, txt, out);
    }

    // 3) split-K tensor-core GEMMs -> RED into d_out
    {
        cudaLaunchConfig_t cfg = {};
        cfg.gridDim  = dim3(16, 4, 2);
        cfg.blockDim = dim3(256);
        cfg.dynamicSmemBytes = GEMM_SMEM;
        cfg.attrs = &attr;
        cfg.numAttrs = 1;
        cudaLaunchKernelEx(&cfg, k_gemm, out);
    }
}